// round 7
// baseline (speedup 1.0000x reference)
#include <cuda_runtime.h>
#include <cstdint>

#define SS 7
#define NC 20
#define PREDC 30                    // NC + 10
#define TGTC  25                    // NC + 5
#define BATCH 16384
#define CELLS (BATCH * SS * SS)     // 802816
#define WCELLS 32                   // cells per warp-tile
#define NWTILES (CELLS / WCELLS)    // 25088
#define WPRED_B (WCELLS * PREDC * 4)    // 3840 B
#define WTGT_B  (WCELLS * TGTC * 4)     // 3200 B
#define WSTAGE_B (WPRED_B + WTGT_B)     // 7040 B
#define NSTAGE 4
#define WARPS 8
#define THREADS (WARPS * 32)
#define SMEM_BYTES (WARPS * NSTAGE * WSTAGE_B)  // 225280 B
#define NBLK 148                    // 1 block/SM
#define NSTREAMS (NBLK * WARPS)     // 1184 independent warp-streams

// ---- TMA bulk copy + mbarrier primitives ----
__device__ __forceinline__ void bulk_g2s(uint32_t dst_smem, const void* src,
                                         uint32_t bytes, uint32_t mbar) {
    asm volatile(
        "cp.async.bulk.shared::cluster.global.mbarrier::complete_tx::bytes "
        "[%0], [%1], %2, [%3];\n"
        :: "r"(dst_smem), "l"(src), "r"(bytes), "r"(mbar) : "memory");
}
__device__ __forceinline__ void mbar_init(uint32_t mbar, uint32_t count) {
    asm volatile("mbarrier.init.shared.b64 [%0], %1;\n" :: "r"(mbar), "r"(count) : "memory");
}
__device__ __forceinline__ void mbar_expect_tx(uint32_t mbar, uint32_t bytes) {
    asm volatile("mbarrier.arrive.expect_tx.shared.b64 _, [%0], %1;\n"
                 :: "r"(mbar), "r"(bytes) : "memory");
}
__device__ __forceinline__ void mbar_wait(uint32_t mbar, uint32_t parity) {
    uint32_t done;
    asm volatile(
        "{\n\t.reg .pred p;\n\t"
        "mbarrier.try_wait.parity.acquire.cta.shared::cta.b64 p, [%1], %2;\n\t"
        "selp.b32 %0, 1, 0, p;\n\t}"
        : "=r"(done) : "r"(mbar), "r"(parity) : "memory");
    if (!done) {
        asm volatile(
            "{\n\t.reg .pred P1;\n\t"
            "WAIT_LOOP_%=:\n\t"
            "mbarrier.try_wait.parity.acquire.cta.shared::cta.b64 P1, [%0], %1, 0x989680;\n\t"
            "@P1 bra.uni WAIT_DONE_%=;\n\t"
            "bra.uni WAIT_LOOP_%=;\n\t"
            "WAIT_DONE_%=:\n\t}"
            :: "r"(mbar), "r"(parity) : "memory");
    }
}

__device__ __forceinline__ float iou_fn(float ax, float ay, float aw, float ah,
                                        float bx, float by, float bw, float bh) {
    float ax1 = ax - aw * 0.5f, ax2 = ax + aw * 0.5f;
    float ay1 = ay - ah * 0.5f, ay2 = ay + ah * 0.5f;
    float bx1 = bx - bw * 0.5f, bx2 = bx + bw * 0.5f;
    float by1 = by - bh * 0.5f, by2 = by + bh * 0.5f;
    float iw = fminf(ax2, bx2) - fmaxf(ax1, bx1); iw = fmaxf(iw, 0.0f);
    float ih = fminf(ay2, by2) - fmaxf(ay1, by1); ih = fmaxf(ih, 0.0f);
    float inter = iw * ih;
    float area_a = fabsf(aw * ah);
    float area_b = fabsf(bw * bh);
    return inter / (area_a + area_b - inter + 1e-6f);
}

// One warp-tile: lane computes its own cell from this warp's stage slot.
__device__ __forceinline__ float compute_wtile(const float* __restrict__ slot, int lane) {
    const float* p = slot + lane * PREDC;
    const float* t = slot + WCELLS * PREDC + lane * TGTC;

    float cls = 0.0f;
    #pragma unroll
    for (int c = 0; c < NC; c++) {
        float d = p[c] - t[c];
        cls = fmaf(d, d, cls);
    }

    float b1x = p[20], b1y = p[21], b1w = p[22], b1h = p[23], b1c = p[24];
    float b2x = p[25], b2y = p[26], b2w = p[27], b2h = p[28], b2c = p[29];
    // tb = targets[..., C:C+5] -> channels 20..24 (channel 20 doubles as obj flag)
    float tx = t[20], ty = t[21], tw = t[22], th = t[23], tc = t[24];
    float obj = (t[20] == 1.0f) ? 1.0f : 0.0f;

    float iou1 = iou_fn(b1x, b1y, b1w, b1h, tx, ty, tw, th);
    float iou2 = iou_fn(b2x, b2y, b2w, b2h, tx, ty, tw, th);
    bool use1 = iou1 > iou2;

    float rx = use1 ? b1x : b2x;
    float ry = use1 ? b1y : b2y;
    float rw = use1 ? b1w : b2w;
    float rh = use1 ? b1h : b2h;
    float rc = use1 ? b1c : b2c;
    float other_conf = use1 ? b2c : b1c;

    float srw = sqrtf(fmaxf(rw, 1e-6f));
    float srh = sqrtf(fmaxf(rh, 1e-6f));
    float stw = sqrtf(fmaxf(tw, 1e-6f));
    float sth = sqrtf(fmaxf(th, 1e-6f));

    float dx = rx - tx, dy = ry - ty, dw = srw - stw, dh = srh - sth;
    float coord = 5.0f * (dx * dx + dy * dy + dw * dw + dh * dh);
    float dc = rc - tc;
    float obj_conf = dc * dc;
    float noobj_in  = 0.5f * other_conf * other_conf;
    float noobj_out = 0.5f * (b1c * b1c + b2c * b2c);

    return obj * (coord + obj_conf + cls + noobj_in) + (1.0f - obj) * noobj_out;
}

__global__ __launch_bounds__(THREADS)
void yolo_loss_kernel(const float* __restrict__ pred,
                      const float* __restrict__ tgt,
                      float* __restrict__ out) {
    extern __shared__ __align__(128) float smem[];
    __shared__ __align__(8) unsigned long long mbar_store[WARPS * NSTAGE];
    __shared__ float warp_sums[WARPS];

    const int tid  = threadIdx.x;
    const int wid  = tid >> 5;
    const int lane = tid & 31;
    const uint32_t sbase = (uint32_t)__cvta_generic_to_shared(smem);
    const uint32_t mb0   = (uint32_t)__cvta_generic_to_shared(mbar_store);

    if (tid == 0) {
        #pragma unroll
        for (int s = 0; s < WARPS * NSTAGE; s++) mbar_init(mb0 + s * 8, 1);
    }
    __syncthreads();

    // Independent warp-stream: contiguous chunk of warp-tiles.
    const int g = blockIdx.x * WARPS + wid;
    const int q = NWTILES / NSTREAMS;       // 21
    const int r = NWTILES % NSTREAMS;       // 224
    const int start = g * q + (g < r ? g : r);
    const int nt = q + (g < r ? 1 : 0);     // 21 or 22 (>= NSTAGE-1)

    const uint32_t wbase  = sbase + wid * (NSTAGE * WSTAGE_B);
    const uint32_t wmbar0 = mb0 + wid * NSTAGE * 8;

    // Producer: lane 0 of this warp issues tile j into slot (j & 3).
    auto issue = [&](int j) {
        const int s = j & (NSTAGE - 1);
        const uint32_t mb = wmbar0 + s * 8;
        const uint32_t dst = wbase + s * WSTAGE_B;
        mbar_expect_tx(mb, WSTAGE_B);
        bulk_g2s(dst, pred + (size_t)(start + j) * WCELLS * PREDC, WPRED_B, mb);
        bulk_g2s(dst + WPRED_B, tgt + (size_t)(start + j) * WCELLS * TGTC, WTGT_B, mb);
    };

    // Prologue: depth-3 prefetch for this warp's stream.
    if (lane == 0) {
        #pragma unroll
        for (int s = 0; s < NSTAGE - 1; s++) issue(s);   // nt >= 21 always
    }

    float acc = 0.0f;
    for (int i = 0; i < nt; i++) {
        const int s = i & (NSTAGE - 1);
        mbar_wait(wmbar0 + s * 8, (i >> 2) & 1);   // this warp's tile i ready
        __syncwarp();                               // all lanes past tile i-1 reads
        if (lane == 0 && i + NSTAGE - 1 < nt) issue(i + NSTAGE - 1);
        acc += compute_wtile(smem + (size_t)wid * (NSTAGE * WSTAGE_B / 4)
                                  + (size_t)s * (WSTAGE_B / 4), lane);
    }

    // Warp reduce, then one atomic per block.
    #pragma unroll
    for (int off = 16; off > 0; off >>= 1)
        acc += __shfl_xor_sync(0xFFFFFFFFu, acc, off);
    if (lane == 0) warp_sums[wid] = acc;
    __syncthreads();
    if (tid == 0) {
        float s = 0.0f;
        #pragma unroll
        for (int w = 0; w < WARPS; w++) s += warp_sums[w];
        atomicAdd(out, s * (1.0f / (float)BATCH));
    }
}

extern "C" void kernel_launch(void* const* d_in, const int* in_sizes, int n_in,
                              void* d_out, int out_size) {
    const float* pred = (const float*)d_in[0];
    const float* tgt  = (const float*)d_in[1];
    float* out = (float*)d_out;
    cudaFuncSetAttribute(yolo_loss_kernel,
                         cudaFuncAttributeMaxDynamicSharedMemorySize, SMEM_BYTES);
    cudaMemsetAsync(out, 0, sizeof(float));
    yolo_loss_kernel<<<NBLK, THREADS, SMEM_BYTES>>>(pred, tgt, out);
}

// round 8
// speedup vs baseline: 1.0520x; 1.0520x over previous
#include <cuda_runtime.h>
#include <cstdint>

#define SS 7
#define NC 20
#define PREDC 30                    // NC + 10
#define TGTC  25                    // NC + 5
#define BATCH 16384
#define CELLS (BATCH * SS * SS)     // 802816
#define CWARPS 7                    // consumer warps
#define TCELLS (CWARPS * 32)        // 224 cells per tile
#define NTILES (CELLS / TCELLS)     // 3584 (exact)
#define PRED_TILE_B (TCELLS * PREDC * 4)   // 26880 B
#define TGT_TILE_B  (TCELLS * TGTC * 4)    // 22400 B
#define STAGE_B (PRED_TILE_B + TGT_TILE_B) // 49280 B
#define NSTAGE 4
#define SMEM_BYTES (NSTAGE * STAGE_B)      // 197120 B
#define THREADS 256                 // warp 0 = producer, warps 1..7 consumers
#define NBLK 148                    // 1 block/SM

// ---- TMA bulk copy + mbarrier primitives ----
__device__ __forceinline__ void bulk_g2s(uint32_t dst_smem, const void* src,
                                         uint32_t bytes, uint32_t mbar) {
    asm volatile(
        "cp.async.bulk.shared::cluster.global.mbarrier::complete_tx::bytes "
        "[%0], [%1], %2, [%3];\n"
        :: "r"(dst_smem), "l"(src), "r"(bytes), "r"(mbar) : "memory");
}
__device__ __forceinline__ void mbar_init(uint32_t mbar, uint32_t count) {
    asm volatile("mbarrier.init.shared.b64 [%0], %1;\n" :: "r"(mbar), "r"(count) : "memory");
}
__device__ __forceinline__ void mbar_expect_tx(uint32_t mbar, uint32_t bytes) {
    asm volatile("mbarrier.arrive.expect_tx.shared.b64 _, [%0], %1;\n"
                 :: "r"(mbar), "r"(bytes) : "memory");
}
__device__ __forceinline__ void mbar_arrive(uint32_t mbar) {
    asm volatile("mbarrier.arrive.shared.b64 _, [%0];\n" :: "r"(mbar) : "memory");
}
__device__ __forceinline__ void mbar_wait(uint32_t mbar, uint32_t parity) {
    uint32_t done;
    asm volatile(
        "{\n\t.reg .pred p;\n\t"
        "mbarrier.try_wait.parity.acquire.cta.shared::cta.b64 p, [%1], %2;\n\t"
        "selp.b32 %0, 1, 0, p;\n\t}"
        : "=r"(done) : "r"(mbar), "r"(parity) : "memory");
    if (!done) {
        asm volatile(
            "{\n\t.reg .pred P1;\n\t"
            "WAIT_LOOP_%=:\n\t"
            "mbarrier.try_wait.parity.acquire.cta.shared::cta.b64 P1, [%0], %1, 0x989680;\n\t"
            "@P1 bra.uni WAIT_DONE_%=;\n\t"
            "bra.uni WAIT_LOOP_%=;\n\t"
            "WAIT_DONE_%=:\n\t}"
            :: "r"(mbar), "r"(parity) : "memory");
    }
}

__device__ __forceinline__ float iou_fn(float ax, float ay, float aw, float ah,
                                        float bx, float by, float bw, float bh) {
    float ax1 = ax - aw * 0.5f, ax2 = ax + aw * 0.5f;
    float ay1 = ay - ah * 0.5f, ay2 = ay + ah * 0.5f;
    float bx1 = bx - bw * 0.5f, bx2 = bx + bw * 0.5f;
    float by1 = by - bh * 0.5f, by2 = by + bh * 0.5f;
    float iw = fminf(ax2, bx2) - fmaxf(ax1, bx1); iw = fmaxf(iw, 0.0f);
    float ih = fminf(ay2, by2) - fmaxf(ay1, by1); ih = fmaxf(ih, 0.0f);
    float inter = iw * ih;
    float area_a = fabsf(aw * ah);
    float area_b = fabsf(bw * bh);
    return inter / (area_a + area_b - inter + 1e-6f);
}

// One cell of loss. slot points at stage base; cell = index within tile.
__device__ __forceinline__ float compute_cell(const float* __restrict__ slot, int cell) {
    const float* p = slot + cell * PREDC;
    const float* t = slot + TCELLS * PREDC + cell * TGTC;

    float cls = 0.0f;
    #pragma unroll
    for (int c = 0; c < NC; c++) {
        float d = p[c] - t[c];
        cls = fmaf(d, d, cls);
    }

    float b1x = p[20], b1y = p[21], b1w = p[22], b1h = p[23], b1c = p[24];
    float b2x = p[25], b2y = p[26], b2w = p[27], b2h = p[28], b2c = p[29];
    // tb = targets[..., C:C+5] -> channels 20..24 (channel 20 doubles as obj flag)
    float tx = t[20], ty = t[21], tw = t[22], th = t[23], tc = t[24];
    float obj = (t[20] == 1.0f) ? 1.0f : 0.0f;

    float iou1 = iou_fn(b1x, b1y, b1w, b1h, tx, ty, tw, th);
    float iou2 = iou_fn(b2x, b2y, b2w, b2h, tx, ty, tw, th);
    bool use1 = iou1 > iou2;

    float rx = use1 ? b1x : b2x;
    float ry = use1 ? b1y : b2y;
    float rw = use1 ? b1w : b2w;
    float rh = use1 ? b1h : b2h;
    float rc = use1 ? b1c : b2c;
    float other_conf = use1 ? b2c : b1c;

    float srw = sqrtf(fmaxf(rw, 1e-6f));
    float srh = sqrtf(fmaxf(rh, 1e-6f));
    float stw = sqrtf(fmaxf(tw, 1e-6f));
    float sth = sqrtf(fmaxf(th, 1e-6f));

    float dx = rx - tx, dy = ry - ty, dw = srw - stw, dh = srh - sth;
    float coord = 5.0f * (dx * dx + dy * dy + dw * dw + dh * dh);
    float dc = rc - tc;
    float obj_conf = dc * dc;
    float noobj_in  = 0.5f * other_conf * other_conf;
    float noobj_out = 0.5f * (b1c * b1c + b2c * b2c);

    return obj * (coord + obj_conf + cls + noobj_in) + (1.0f - obj) * noobj_out;
}

__global__ __launch_bounds__(THREADS)
void yolo_loss_kernel(const float* __restrict__ pred,
                      const float* __restrict__ tgt,
                      float* __restrict__ out) {
    extern __shared__ __align__(128) float smem[];
    // full[s] at +s*16, empty[s] at +s*16+8 (interleaved ring)
    __shared__ __align__(8) unsigned long long mbar_store[NSTAGE * 2];
    __shared__ float warp_sums[THREADS / 32];

    const int tid  = threadIdx.x;
    const int wid  = tid >> 5;
    const int lane = tid & 31;
    const uint32_t sbase = (uint32_t)__cvta_generic_to_shared(smem);
    const uint32_t mb0   = (uint32_t)__cvta_generic_to_shared(mbar_store);

    if (tid == 0) {
        #pragma unroll
        for (int s = 0; s < NSTAGE; s++) {
            mbar_init(mb0 + s * 16,     1);        // full: producer expect_tx arrive
            mbar_init(mb0 + s * 16 + 8, CWARPS);   // empty: one arrive per consumer warp
        }
    }
    __syncthreads();   // barriers visible before any producer/consumer op

    // Balanced contiguous partition of tiles across blocks.
    const int q = NTILES / NBLK;            // 24
    const int r = NTILES % NBLK;            // 32
    const int bid = blockIdx.x;
    const int start = bid * q + (bid < r ? bid : r);
    const int nt = q + (bid < r ? 1 : 0);   // 24 or 25

    if (wid == 0) {
        // ---------------- Producer warp ----------------
        if (lane == 0) {
            for (int j = 0; j < nt; j++) {
                const int s = j & (NSTAGE - 1);
                // Empty-wait: fresh barrier passes parity=1 immediately (first lap).
                mbar_wait(mb0 + s * 16 + 8, 1u ^ ((j >> 2) & 1));
                const uint32_t fb = mb0 + s * 16;
                const uint32_t dst = sbase + s * STAGE_B;
                mbar_expect_tx(fb, STAGE_B);
                bulk_g2s(dst, pred + (size_t)(start + j) * TCELLS * PREDC, PRED_TILE_B, fb);
                bulk_g2s(dst + PRED_TILE_B,
                         tgt + (size_t)(start + j) * TCELLS * TGTC, TGT_TILE_B, fb);
            }
        }
        if (lane == 0) warp_sums[0] = 0.0f;
    } else {
        // ---------------- Consumer warps (1..7) ----------------
        const int cell = (wid - 1) * 32 + lane;   // this thread's cell within every tile
        float acc = 0.0f;
        for (int i = 0; i < nt; i++) {
            const int s = i & (NSTAGE - 1);
            mbar_wait(mb0 + s * 16, (i >> 2) & 1);      // full (acquire)
            acc += compute_cell(smem + (size_t)s * (STAGE_B / 4), cell);
            __syncwarp();                                // all lanes done reading slot
            if (lane == 0) mbar_arrive(mb0 + s * 16 + 8); // release empty
        }
        // Warp reduce
        #pragma unroll
        for (int off = 16; off > 0; off >>= 1)
            acc += __shfl_xor_sync(0xFFFFFFFFu, acc, off);
        if (lane == 0) warp_sums[wid] = acc;
    }

    __syncthreads();
    if (tid == 0) {
        float s = 0.0f;
        #pragma unroll
        for (int w = 0; w < THREADS / 32; w++) s += warp_sums[w];
        atomicAdd(out, s * (1.0f / (float)BATCH));
    }
}

extern "C" void kernel_launch(void* const* d_in, const int* in_sizes, int n_in,
                              void* d_out, int out_size) {
    const float* pred = (const float*)d_in[0];
    const float* tgt  = (const float*)d_in[1];
    float* out = (float*)d_out;
    cudaFuncSetAttribute(yolo_loss_kernel,
                         cudaFuncAttributeMaxDynamicSharedMemorySize, SMEM_BYTES);
    cudaMemsetAsync(out, 0, sizeof(float));
    yolo_loss_kernel<<<NBLK, THREADS, SMEM_BYTES>>>(pred, tgt, out);
}